// round 10
// baseline (speedup 1.0000x reference)
#include <cuda_runtime.h>

#define NBINS 2000
#define NBPAD 2048
#define BIN_STRIDE 64                     /* u32s: 256 bytes between bins */
#define FRAC_BITS 8
#define FRAC_INV_F 0.00390625f            /* 2^-8 */
#define CNT_SHIFT 20
#define SUM_MASK  0x000FFFFFu             /* low 20 bits */
#define LOG2E 1.4426950408889634f
#define GRID_X 592
#define BLOCK_X 512

// Persistent scratch (zero-init at load; last block self-cleans each replay).
// One bin per 256B so L2 atomic serialization spreads across LTS partitions.
__device__ unsigned int g_bins32[NBPAD * BIN_STRIDE];
__device__ double g_neg;             // sum of exp(Yhat)*2^8 over Y<0 (scaled)
__device__ double g_yhat;            // sum of Yhat over Y>0 (loss1)
__device__ unsigned int g_done;      // last-block-done counter

// ---------------------------------------------------------------------------
// Fused: global REDG histogram (no smem privatization) + last-block finalize.
// Per positive element: FFMA + EX2 + FADD(magic) + LOP + IADD + RED.E.ADD.32.
// ---------------------------------------------------------------------------
__global__ void __launch_bounds__(BLOCK_X) surv_fused(
    const float* __restrict__ Yhat, const float* __restrict__ Y, int n,
    float* __restrict__ out, int out_size)
{
    float negAcc = 0.f, yhatAcc = 0.f;

    const int n4 = n >> 2;
    const float4* Yh4 = (const float4*)Yhat;
    const float4* Y4  = (const float4*)Y;
    const int stride = gridDim.x * BLOCK_X;

    #pragma unroll 2
    for (int i = blockIdx.x * BLOCK_X + threadIdx.x; i < n4; i += stride) {
        float4 yh = Yh4[i];
        float4 yy = Y4[i];
        float hv[4] = {yh.x, yh.y, yh.z, yh.w};
        float yv[4] = {yy.x, yy.y, yy.z, yy.w};
        #pragma unroll
        for (int k = 0; k < 4; k++) {
            // e2 = exp(hv)*2^8 : one FFMA + one MUFU.EX2
            float e2 = exp2f(fmaf(hv[k], LOG2E, (float)FRAC_BITS));
            if (yv[k] > 0.f) {
                int t = (((int)yv[k]) - 1) & (NBPAD - 1);   // 0..2047, OOB-safe
                // round-to-nearest int via 2^23 magic add (e2 < 2^16 << 2^23)
                unsigned int q = __float_as_uint(e2 + 8388608.0f) & 0x007FFFFFu;
                atomicAdd(&g_bins32[t * BIN_STRIDE], (1u << CNT_SHIFT) + q);
                yhatAcc += hv[k];
            } else {
                negAcc += e2;     // scaled by 2^8; stays scaled through finalize
            }
        }
    }

    // scalar tail (n is a multiple of 4 here; kept for generality)
    if (blockIdx.x == 0 && threadIdx.x == 0) {
        for (int i = n4 << 2; i < n; i++) {
            float e2 = exp2f(fmaf(Yhat[i], LOG2E, (float)FRAC_BITS));
            float y = Y[i];
            if (y > 0.f) {
                int t = (((int)y) - 1) & (NBPAD - 1);
                unsigned int q = __float_as_uint(e2 + 8388608.0f) & 0x007FFFFFu;
                atomicAdd(&g_bins32[t * BIN_STRIDE], (1u << CNT_SHIFT) + q);
                yhatAcc += Yhat[i];
            } else {
                negAcc += e2;
            }
        }
    }

    // Block-reduce negAcc / yhatAcc -> one double atomic per block
    const int lane = threadIdx.x & 31, wid = threadIdx.x >> 5;
    #pragma unroll
    for (int d = 16; d; d >>= 1) {
        negAcc  += __shfl_down_sync(0xffffffffu, negAcc,  d);
        yhatAcc += __shfl_down_sync(0xffffffffu, yhatAcc, d);
    }
    __shared__ float wNeg[16], wYh[16];
    if (lane == 0) { wNeg[wid] = negAcc; wYh[wid] = yhatAcc; }
    __syncthreads();
    if (wid == 0 && lane < 16) {
        float a = wNeg[lane];
        float b = wYh[lane];
        #pragma unroll
        for (int d = 8; d; d >>= 1) {
            a += __shfl_down_sync(0x0000ffffu, a, d);
            b += __shfl_down_sync(0x0000ffffu, b, d);
        }
        if (lane == 0) {
            atomicAdd(&g_neg,  (double)a);
            atomicAdd(&g_yhat, (double)b);
        }
    }

    // ---- last-block-done handoff ----
    __shared__ bool isLast;
    __threadfence();
    if (threadIdx.x == 0) {
        unsigned int prev = atomicAdd(&g_done, 1u);
        isLast = (prev == gridDim.x - 1);
    }
    __syncthreads();
    if (!isLast) return;
    __threadfence();   // acquire all other blocks' writes

    // ================= FINALIZE (512 threads, 4 bins/thread) ================
    const int tid = threadIdx.x;
    unsigned long long s[4];
    unsigned int c[4];
    const int bbase = 4 * tid;
    unsigned long long mySum = 0ULL;
    #pragma unroll
    for (int k = 0; k < 4; k++) {
        s[k] = 0ULL; c[k] = 0u;
        int b = bbase + k;
        if (b < NBINS) {
            unsigned int p = g_bins32[b * BIN_STRIDE];
            s[k] = (unsigned long long)(p & SUM_MASK);
            c[k] = p >> CNT_SHIFT;
            mySum += s[k];
        }
    }

    // exclusive scan of mySum across 512 threads (exact u64, 2^8 units)
    unsigned long long x = mySum;
    #pragma unroll
    for (int d = 1; d < 32; d <<= 1) {
        unsigned long long nv = __shfl_up_sync(0xffffffffu, x, d);
        if (lane >= d) x += nv;
    }
    __shared__ unsigned long long wsum[16];
    if (lane == 31) wsum[wid] = x;
    __syncthreads();
    if (wid == 0 && lane < 16) {
        unsigned long long w = wsum[lane];
        #pragma unroll
        for (int d = 1; d < 16; d <<= 1) {
            unsigned long long nv = __shfl_up_sync(0x0000ffffu, w, d);
            if (lane >= d) w += nv;
        }
        wsum[lane] = w;
    }
    __syncthreads();

    unsigned long long excl = ((wid > 0) ? wsum[wid - 1] : 0ULL) + (x - mySum);

    // g_neg already in 2^8 fixed-point units
    unsigned long long negQ = (unsigned long long)(g_neg + 0.5);

    unsigned long long run = negQ + excl;
    float loss2 = 0.f;
    unsigned int obs = 0u;
    #pragma unroll
    for (int k = 0; k < 4; k++) {
        run += s[k];
        if (c[k] > 0u) {
            loss2 += (float)c[k] * __logf((float)run * FRAC_INV_F);
            obs += c[k];
        }
    }

    // block reduce (loss2 float, obs int)
    #pragma unroll
    for (int d = 16; d; d >>= 1) {
        loss2 += __shfl_down_sync(0xffffffffu, loss2, d);
        obs   += __shfl_down_sync(0xffffffffu, obs, d);
    }
    __shared__ float sL[16];
    __shared__ unsigned int sO[16];
    if (lane == 0) { sL[wid] = loss2; sO[wid] = obs; }
    __syncthreads();
    if (tid == 0) {
        double L = 0.0; unsigned long long O = 0;
        #pragma unroll
        for (int w = 0; w < 16; w++) { L += (double)sL[w]; O += sO[w]; }
        double loss = (L - g_yhat) / (double)O;
        for (int j = 0; j < out_size; j++) out[j] = (float)loss;
    }
    __syncthreads();

    // self-clean the used slots for the next graph replay
    for (int i = tid; i < NBINS; i += BLOCK_X) g_bins32[i * BIN_STRIDE] = 0u;
    if (tid == 0) { g_neg = 0.0; g_yhat = 0.0; g_done = 0u; }
}

extern "C" void kernel_launch(void* const* d_in, const int* in_sizes, int n_in,
                              void* d_out, int out_size)
{
    const float* Yhat = (const float*)d_in[0];
    const float* Y    = (const float*)d_in[1];
    int n = in_sizes[0];

    surv_fused<<<GRID_X, BLOCK_X>>>(Yhat, Y, n, (float*)d_out, out_size);
}

// round 11
// speedup vs baseline: 1.9763x; 1.9763x over previous
#include <cuda_runtime.h>

#define NBINS 2000
#define NBPAD 2048
#define FRAC_BITS 14
#define FRAC_INV_F   6.103515625e-5f     /* 2^-14 */
#define SUM_MASK64   0xFFFFFFFFFFULL     /* low 40 bits of global packing */
#define SUM_MASK32   0x01FFFFFFu         /* low 25 bits of block packing */
#define CNT_SHIFT32  25
#define LOG2E 1.4426950408889634f
#define GRID_X 296
#define BLOCK_X 1024

// Persistent scratch (zero-init at load; last block self-cleans each replay).
__device__ unsigned long long g_bins[NBINS];
__device__ double g_all;             // sum of exp(Yhat)*2^14 over ALL samples
__device__ double g_yhat;            // sum of Yhat over Y>0 (loss1)
__device__ unsigned int g_done;      // last-block-done counter

// ---------------------------------------------------------------------------
// Fused: u32 shared-atomic histogram + last-block finalize.
// Hot path: FFMA+EX2+FADD(all)+F2I/IADD/LOP(t)+FADD(magic)/LOP/IADD(q)
//           + FSETP + @P{ATOMS.32, FADD}.  No BSSY/BSYNC in the loop.
// ---------------------------------------------------------------------------
__global__ void __launch_bounds__(BLOCK_X) surv_fused(
    const float* __restrict__ Yhat, const float* __restrict__ Y, int n,
    float* __restrict__ out, int out_size)
{
    __shared__ unsigned int sBins[NBPAD];
    for (int i = threadIdx.x; i < NBPAD; i += BLOCK_X) sBins[i] = 0u;
    __syncthreads();

    float allAcc = 0.f, yhatAcc = 0.f;

    const int n4 = n >> 2;
    const float4* Yh4 = (const float4*)Yhat;
    const float4* Y4  = (const float4*)Y;
    const int stride = gridDim.x * BLOCK_X;

    for (int i = blockIdx.x * BLOCK_X + threadIdx.x; i < n4; i += stride) {
        float4 yh = Yh4[i];
        float4 yy = Y4[i];
        float hv[4] = {yh.x, yh.y, yh.z, yh.w};
        float yv[4] = {yy.x, yy.y, yy.z, yy.w};
        #pragma unroll
        for (int k = 0; k < 4; k++) {
            // e2 = exp(hv)*2^14 : one FFMA + one MUFU.EX2
            float e2 = exp2f(fmaf(hv[k], LOG2E, (float)FRAC_BITS));
            allAcc += e2;                                // unconditional
            int t = (((int)yv[k]) - 1) & (NBPAD - 1);    // OOB-safe bin
            unsigned int q =
                (__float_as_uint(e2 + 8388608.0f) & 0x007FFFFFu) + (1u << CNT_SHIFT32);
            if (yv[k] > 0.f) {                           // 2-instr body -> @P
                atomicAdd(&sBins[t], q);
                yhatAcc += hv[k];
            }
        }
    }

    // scalar tail (n is a multiple of 4 here; kept for generality)
    if (blockIdx.x == 0 && threadIdx.x == 0) {
        for (int i = n4 << 2; i < n; i++) {
            float e2 = exp2f(fmaf(Yhat[i], LOG2E, (float)FRAC_BITS));
            allAcc += e2;
            float y = Y[i];
            int t = (((int)y) - 1) & (NBPAD - 1);
            unsigned int q =
                (__float_as_uint(e2 + 8388608.0f) & 0x007FFFFFu) + (1u << CNT_SHIFT32);
            if (y > 0.f) {
                atomicAdd(&sBins[t], q);
                yhatAcc += Yhat[i];
            }
        }
    }

    __syncthreads();

    // Flush shared histogram to global u64 packing (deterministic integer adds)
    for (int i = threadIdx.x; i < NBINS; i += BLOCK_X) {
        unsigned int v = sBins[i];
        if (v) {
            unsigned long long packed =
                ((unsigned long long)(v >> CNT_SHIFT32) << 40) |
                (unsigned long long)(v & SUM_MASK32);
            atomicAdd(&g_bins[i], packed);
        }
    }

    // Block-reduce allAcc / yhatAcc -> one double atomic per block
    const int lane = threadIdx.x & 31, wid = threadIdx.x >> 5;
    #pragma unroll
    for (int d = 16; d; d >>= 1) {
        allAcc  += __shfl_down_sync(0xffffffffu, allAcc,  d);
        yhatAcc += __shfl_down_sync(0xffffffffu, yhatAcc, d);
    }
    __shared__ float wAll[32], wYh[32];
    if (lane == 0) { wAll[wid] = allAcc; wYh[wid] = yhatAcc; }
    __syncthreads();
    if (wid == 0) {
        float a = wAll[lane];
        float b = wYh[lane];
        #pragma unroll
        for (int d = 16; d; d >>= 1) {
            a += __shfl_down_sync(0xffffffffu, a, d);
            b += __shfl_down_sync(0xffffffffu, b, d);
        }
        if (lane == 0) {
            atomicAdd(&g_all,  (double)a);
            atomicAdd(&g_yhat, (double)b);
        }
    }

    // ---- last-block-done handoff ----
    __shared__ bool isLast;
    __threadfence();
    if (threadIdx.x == 0) {
        unsigned int prev = atomicAdd(&g_done, 1u);
        isLast = (prev == gridDim.x - 1);
    }
    __syncthreads();
    if (!isLast) return;
    __threadfence();   // acquire all other blocks' writes

    // ================ FINALIZE (1024 threads, 2 bins/thread) ================
    const int tid = threadIdx.x;
    unsigned long long s0 = 0ULL, s1 = 0ULL;
    unsigned int c0 = 0u, c1 = 0u;
    int b0 = 2 * tid, b1 = 2 * tid + 1;
    if (b0 < NBINS) {
        unsigned long long p = g_bins[b0];
        s0 = p & SUM_MASK64;
        c0 = (unsigned int)(p >> 40);
    }
    if (b1 < NBINS) {
        unsigned long long p = g_bins[b1];
        s1 = p & SUM_MASK64;
        c1 = (unsigned int)(p >> 40);
    }
    unsigned long long mySum = s0 + s1;

    // inclusive scan of mySum across 1024 threads (exact u64)
    unsigned long long x = mySum;
    #pragma unroll
    for (int d = 1; d < 32; d <<= 1) {
        unsigned long long nv = __shfl_up_sync(0xffffffffu, x, d);
        if (lane >= d) x += nv;
    }
    __shared__ unsigned long long wsum[32];
    if (lane == 31) wsum[wid] = x;
    __syncthreads();
    if (wid == 0) {
        unsigned long long w = wsum[lane];
        #pragma unroll
        for (int d = 1; d < 32; d <<= 1) {
            unsigned long long nv = __shfl_up_sync(0xffffffffu, w, d);
            if (lane >= d) w += nv;
        }
        wsum[lane] = w;
    }
    __syncthreads();

    unsigned long long base = (wid > 0) ? wsum[wid - 1] : 0ULL;
    unsigned long long excl = base + (x - mySum);
    unsigned long long binTotal = wsum[31];   // total over all positive bins

    // S_neg (2^14 units) = total over everything - total over positives
    unsigned long long negQ = (unsigned long long)(g_all + 0.5) - binTotal;

    unsigned long long P0q = negQ + excl + s0;
    unsigned long long P1q = P0q + s1;

    float loss2 = 0.f;
    unsigned int obs = c0 + c1;
    if (c0 > 0u) loss2 += (float)c0 * __logf((float)P0q * FRAC_INV_F);
    if (c1 > 0u) loss2 += (float)c1 * __logf((float)P1q * FRAC_INV_F);

    // block reduce (loss2 float, obs int)
    #pragma unroll
    for (int d = 16; d; d >>= 1) {
        loss2 += __shfl_down_sync(0xffffffffu, loss2, d);
        obs   += __shfl_down_sync(0xffffffffu, obs, d);
    }
    __shared__ float sL[32];
    __shared__ unsigned int sO[32];
    if (lane == 0) { sL[wid] = loss2; sO[wid] = obs; }
    __syncthreads();
    if (tid == 0) {
        double L = 0.0; unsigned long long O = 0;
        #pragma unroll
        for (int w = 0; w < 32; w++) { L += (double)sL[w]; O += sO[w]; }
        double loss = (L - g_yhat) / (double)O;
        for (int j = 0; j < out_size; j++) out[j] = (float)loss;
    }
    __syncthreads();

    // self-clean for the next graph replay
    for (int i = tid; i < NBINS; i += BLOCK_X) g_bins[i] = 0ULL;
    if (tid == 0) { g_all = 0.0; g_yhat = 0.0; g_done = 0u; }
}

extern "C" void kernel_launch(void* const* d_in, const int* in_sizes, int n_in,
                              void* d_out, int out_size)
{
    const float* Yhat = (const float*)d_in[0];
    const float* Y    = (const float*)d_in[1];
    int n = in_sizes[0];

    surv_fused<<<GRID_X, BLOCK_X>>>(Yhat, Y, n, (float*)d_out, out_size);
}